// round 5
// baseline (speedup 1.0000x reference)
#include <cuda_runtime.h>
#include <math.h>

#define B_ 4
#define N_ 4096
#define J_ 512
#define DIM_ 1024
#define CTX_ 768
#define HEADS_ 16
#define DH_ 64
#define HID_ 1024
#define ROWS_ (B_ * N_)          // 16384
#define CTXROWS_ (B_ * J_)       // 2048
#define KVW_ (2 * HID_)          // 2048

// ---------------- scratch (device globals; no allocation allowed) ----------------
__device__ float g_xn[(size_t)ROWS_ * DIM_];
__device__ float g_q[(size_t)ROWS_ * HID_];
__device__ float g_kv[(size_t)CTXROWS_ * KVW_];
__device__ float g_att[(size_t)ROWS_ * HID_];
__device__ float g_o[(size_t)ROWS_ * DIM_];
__device__ unsigned char g_fullmask[B_ * J_];

// ---------------- mask prep with dtype sniffing ----------------
// mask is jnp bool [B, J-1]. The harness may hand it to us as 1-byte bools or
// widened to int32/float32. Sniff: read the first 511 32-bit words; if every
// word is 0, 1, or 0x3F800000 (1.0f) it is a 4-byte element stream (prob. of a
// random packed-byte stream passing this for all 511 words is ~(2/16)^511 ~ 0).
__global__ void prep_mask_kernel(const void* __restrict__ mraw) {
    __shared__ int four_byte;
    if (threadIdx.x == 0) {
        const unsigned int* mi = (const unsigned int*)mraw;
        int ok = 1;
        for (int i = 0; i < (J_ - 1); i++) {
            unsigned int v = mi[i];
            if (!(v == 0u || v == 1u || v == 0x3F800000u)) { ok = 0; break; }
        }
        four_byte = ok;
    }
    __syncthreads();
    const int f = four_byte;
    for (int idx = threadIdx.x; idx < B_ * J_; idx += blockDim.x) {
        int b = idx >> 9;
        int j = idx & (J_ - 1);
        unsigned char m;
        if (j == 0) {
            m = 1;  // full_mask padded True at j==0
        } else {
            int off = b * (J_ - 1) + (j - 1);
            if (f) m = (((const unsigned int*)mraw)[off] != 0u) ? 1 : 0;
            else   m = (((const unsigned char*)mraw)[off] != 0) ? 1 : 0;
        }
        g_fullmask[idx] = m;
    }
}

// ---------------- gamma-only LayerNorm over 1024 cols ----------------
__global__ void ln_kernel(const float* __restrict__ in, const float* __restrict__ gamma,
                          float* __restrict__ out) {
    __shared__ float red_s[8];
    __shared__ float red_q[8];
    const size_t row = blockIdx.x;
    const int t = threadIdx.x;  // 256 threads, one float4 each
    float4 v = ((const float4*)(in + row * DIM_))[t];
    float s = v.x + v.y + v.z + v.w;
    float q = v.x * v.x + v.y * v.y + v.z * v.z + v.w * v.w;
#pragma unroll
    for (int o = 16; o > 0; o >>= 1) {
        s += __shfl_xor_sync(0xffffffffu, s, o);
        q += __shfl_xor_sync(0xffffffffu, q, o);
    }
    const int w = t >> 5, lane = t & 31;
    if (lane == 0) { red_s[w] = s; red_q[w] = q; }
    __syncthreads();
    float ts = 0.f, tq = 0.f;
#pragma unroll
    for (int i = 0; i < 8; i++) { ts += red_s[i]; tq += red_q[i]; }
    const float mu = ts * (1.0f / DIM_);
    const float var = tq * (1.0f / DIM_) - mu * mu;
    const float rs = rsqrtf(var + 1e-5f);
    float4 g = ((const float4*)gamma)[t];
    float4 o4;
    o4.x = (v.x - mu) * rs * g.x;
    o4.y = (v.y - mu) * rs * g.y;
    o4.z = (v.z - mu) * rs * g.z;
    o4.w = (v.w - mu) * rs * g.w;
    ((float4*)(out + row * DIM_))[t] = o4;
}

// ---------------- classic SGEMM: C[M,N] = A[M,K] @ B[K,N] ----------------
// BM=BN=128, BK=8, 256 threads, 8x8 microtile.
// Register prefetch + double-buffered smem: ONE __syncthreads per k-tile.
// All dims divisible (M in {16384,2048}, N in {1024,2048}, K in {1024,768}).
__global__ void __launch_bounds__(256)
sgemm_kernel(const float* __restrict__ A, const float* __restrict__ Bm,
             float* __restrict__ C, int M, int N, int K) {
    __shared__ float As[2][8][128];
    __shared__ float Bs[2][8][128];
    const int tx = threadIdx.x;
    const int r0 = (tx >> 4) * 8;
    const int c0 = (tx & 15) * 8;
    const float* Ablk = A + (size_t)blockIdx.y * 128 * K;
    const float* Bblk = Bm + (size_t)blockIdx.x * 128;
    const int a_row = tx >> 1;
    const int a_col = (tx & 1) * 4;
    const int b_row = tx >> 5;
    const int b_col = (tx & 31) * 4;
    float acc[8][8];
#pragma unroll
    for (int i = 0; i < 8; i++)
#pragma unroll
        for (int j = 0; j < 8; j++) acc[i][j] = 0.f;

    // prologue: tile 0 -> regs -> smem buf 0
    {
        float4 av = *(const float4*)(Ablk + (size_t)a_row * K + a_col);
        float4 bv = *(const float4*)(Bblk + (size_t)b_row * N + b_col);
        As[0][a_col + 0][a_row] = av.x;
        As[0][a_col + 1][a_row] = av.y;
        As[0][a_col + 2][a_row] = av.z;
        As[0][a_col + 3][a_row] = av.w;
        *(float4*)&Bs[0][b_row][b_col] = bv;
    }
    __syncthreads();

    int p = 0;
#pragma unroll 1
    for (int k0 = 0; k0 < K; k0 += 8) {
        const int has_next = (k0 + 8 < K);
        float4 av, bv;
        if (has_next) {  // prefetch next tile into registers
            av = *(const float4*)(Ablk + (size_t)a_row * K + (k0 + 8) + a_col);
            bv = *(const float4*)(Bblk + (size_t)(k0 + 8 + b_row) * N + b_col);
        }
#pragma unroll
        for (int kk = 0; kk < 8; kk++) {
            float ar[8], br[8];
            float4 t0 = *(const float4*)&As[p][kk][r0];
            float4 t1 = *(const float4*)&As[p][kk][r0 + 4];
            ar[0] = t0.x; ar[1] = t0.y; ar[2] = t0.z; ar[3] = t0.w;
            ar[4] = t1.x; ar[5] = t1.y; ar[6] = t1.z; ar[7] = t1.w;
            float4 u0 = *(const float4*)&Bs[p][kk][c0];
            float4 u1 = *(const float4*)&Bs[p][kk][c0 + 4];
            br[0] = u0.x; br[1] = u0.y; br[2] = u0.z; br[3] = u0.w;
            br[4] = u1.x; br[5] = u1.y; br[6] = u1.z; br[7] = u1.w;
#pragma unroll
            for (int i = 0; i < 8; i++)
#pragma unroll
                for (int j = 0; j < 8; j++) acc[i][j] = fmaf(ar[i], br[j], acc[i][j]);
        }
        if (has_next) {  // commit prefetched tile to the other buffer
            const int np = p ^ 1;
            As[np][a_col + 0][a_row] = av.x;
            As[np][a_col + 1][a_row] = av.y;
            As[np][a_col + 2][a_row] = av.z;
            As[np][a_col + 3][a_row] = av.w;
            *(float4*)&Bs[np][b_row][b_col] = bv;
            __syncthreads();
            p = np;
        }
    }
    float* Cblk = C + (size_t)(blockIdx.y * 128 + r0) * N + blockIdx.x * 128 + c0;
#pragma unroll
    for (int i = 0; i < 8; i++) {
        float4 w0, w1;
        w0.x = acc[i][0]; w0.y = acc[i][1]; w0.z = acc[i][2]; w0.w = acc[i][3];
        w1.x = acc[i][4]; w1.y = acc[i][5]; w1.z = acc[i][6]; w1.w = acc[i][7];
        *(float4*)(Cblk + (size_t)i * N) = w0;
        *(float4*)(Cblk + (size_t)i * N + 4) = w1;
    }
}

// ---------------- attention: one CTA per (b, h, 64 Q rows) ----------------
// Full 64x512 score tile lives in smem -> exact (non-online) softmax.
#define QK_PAD 68
#define S_PAD 520
#define ATT_SMEM_FLOATS (2 * 64 * QK_PAD + 64 * S_PAD)
#define ATT_SMEM_BYTES (ATT_SMEM_FLOATS * 4)
#define SCALE_ 0.125f  // DIM_HEAD^-0.5

__global__ void __launch_bounds__(256)
attn_kernel(const float* __restrict__ q, const float* __restrict__ kv,
            float* __restrict__ outp) {
    extern __shared__ float sm[];
    float* Qt = sm;                    // [64 d][QK_PAD] transposed Q tile
    float* KV = sm + 64 * QK_PAD;      // K chunk transposed / V chunk row-major
    float* S  = sm + 2 * 64 * QK_PAD;  // [64 rows][S_PAD]
    const int tx = threadIdx.x;
    const int n0 = blockIdx.x * 64;
    const int h = blockIdx.y;
    const int b = blockIdx.z;
    const int r0 = (tx >> 4) * 4;
    const int c0 = (tx & 15) * 4;

    // load Q tile transposed: Qt[d][i]
    const float* qbase = q + ((size_t)(b * N_ + n0) * HID_) + h * DH_;
    for (int e = tx; e < 64 * 64; e += 256) {
        int i = e >> 6, d = e & 63;
        Qt[d * QK_PAD + i] = qbase[(size_t)i * HID_ + d];
    }
    __syncthreads();

    // S = scale * Q @ K^T with mask
    for (int jc = 0; jc < 8; jc++) {
        const int jbase = jc * 64;
        const float* kbase = kv + ((size_t)(b * J_ + jbase) * KVW_) + h * DH_;
        for (int e = tx; e < 64 * 64; e += 256) {
            int j = e >> 6, d = e & 63;
            KV[d * QK_PAD + j] = kbase[(size_t)j * KVW_ + d];
        }
        __syncthreads();
        float acc[4][4];
#pragma unroll
        for (int i = 0; i < 4; i++)
#pragma unroll
            for (int j = 0; j < 4; j++) acc[i][j] = 0.f;
#pragma unroll
        for (int d = 0; d < 64; d++) {
            float a[4], bk[4];
#pragma unroll
            for (int i = 0; i < 4; i++) a[i] = Qt[d * QK_PAD + r0 + i];
#pragma unroll
            for (int j = 0; j < 4; j++) bk[j] = KV[d * QK_PAD + c0 + j];
#pragma unroll
            for (int i = 0; i < 4; i++)
#pragma unroll
                for (int j = 0; j < 4; j++) acc[i][j] = fmaf(a[i], bk[j], acc[i][j]);
        }
#pragma unroll
        for (int i = 0; i < 4; i++)
#pragma unroll
            for (int j = 0; j < 4; j++) {
                int jg = jbase + c0 + j;
                S[(r0 + i) * S_PAD + jg] =
                    g_fullmask[b * J_ + jg] ? acc[i][j] * SCALE_ : -1e30f;
            }
        __syncthreads();
    }

    // softmax: each warp owns 8 rows
    {
        const int w = tx >> 5, lane = tx & 31;
        for (int rr = 0; rr < 8; rr++) {
            float* srow = S + (w * 8 + rr) * S_PAD;
            float mx = -1e30f;
            for (int j = lane; j < J_; j += 32) mx = fmaxf(mx, srow[j]);
#pragma unroll
            for (int o = 16; o > 0; o >>= 1) mx = fmaxf(mx, __shfl_xor_sync(0xffffffffu, mx, o));
            float sum = 0.f;
            for (int j = lane; j < J_; j += 32) {
                float e = expf(srow[j] - mx);
                srow[j] = e;
                sum += e;
            }
#pragma unroll
            for (int o = 16; o > 0; o >>= 1) sum += __shfl_xor_sync(0xffffffffu, sum, o);
            float inv = 1.0f / sum;
            for (int j = lane; j < J_; j += 32) srow[j] *= inv;
        }
    }
    __syncthreads();

    // O = P @ V
    float o[4][4];
#pragma unroll
    for (int i = 0; i < 4; i++)
#pragma unroll
        for (int j = 0; j < 4; j++) o[i][j] = 0.f;
    for (int jc = 0; jc < 8; jc++) {
        const int jbase = jc * 64;
        const float* vbase = kv + ((size_t)(b * J_ + jbase) * KVW_) + HID_ + h * DH_;
        for (int e = tx; e < 64 * 64; e += 256) {
            int j = e >> 6, t = e & 63;
            KV[j * QK_PAD + t] = vbase[(size_t)j * KVW_ + t];
        }
        __syncthreads();
#pragma unroll 8
        for (int j = 0; j < 64; j++) {
            float p[4], v4[4];
#pragma unroll
            for (int i = 0; i < 4; i++) p[i] = S[(r0 + i) * S_PAD + jbase + j];
#pragma unroll
            for (int t = 0; t < 4; t++) v4[t] = KV[j * QK_PAD + c0 + t];
#pragma unroll
            for (int i = 0; i < 4; i++)
#pragma unroll
                for (int t = 0; t < 4; t++) o[i][t] = fmaf(p[i], v4[t], o[i][t]);
        }
        __syncthreads();
    }
    // write back into [B, N, H*d] layout (head-transpose folded in)
    float* ob = outp + ((size_t)(b * N_ + n0 + r0) * HID_) + h * DH_ + c0;
#pragma unroll
    for (int i = 0; i < 4; i++) {
        float4 w;
        w.x = o[i][0]; w.y = o[i][1]; w.z = o[i][2]; w.w = o[i][3];
        *(float4*)(ob + (size_t)i * HID_) = w;
    }
}

// ---------------- launch ----------------
extern "C" void kernel_launch(void* const* d_in, const int* in_sizes, int n_in,
                              void* d_out, int out_size) {
    const float* x    = (const float*)d_in[0];
    const float* ctx  = (const float*)d_in[1];
    const void*  mask = d_in[2];
    const float* gx   = (const float*)d_in[3];
    const float* Wq   = (const float*)d_in[4];
    const float* Wkv  = (const float*)d_in[5];
    const float* Wo   = (const float*)d_in[6];
    const float* gout = (const float*)d_in[7];
    float* out = (float*)d_out;

    float *xn, *q, *kv, *att, *o;
    cudaGetSymbolAddress((void**)&xn, g_xn);
    cudaGetSymbolAddress((void**)&q, g_q);
    cudaGetSymbolAddress((void**)&kv, g_kv);
    cudaGetSymbolAddress((void**)&att, g_att);
    cudaGetSymbolAddress((void**)&o, g_o);

    cudaFuncSetAttribute(attn_kernel, cudaFuncAttributeMaxDynamicSharedMemorySize,
                         ATT_SMEM_BYTES);

    prep_mask_kernel<<<1, 512>>>(mask);
    ln_kernel<<<ROWS_, 256>>>(x, gx, xn);
    sgemm_kernel<<<dim3(HID_ / 128, ROWS_ / 128), 256>>>(xn, Wq, q, ROWS_, HID_, DIM_);
    sgemm_kernel<<<dim3(KVW_ / 128, CTXROWS_ / 128), 256>>>(ctx, Wkv, kv, CTXROWS_, KVW_, CTX_);
    attn_kernel<<<dim3(N_ / 64, HEADS_, B_), 256, ATT_SMEM_BYTES>>>(q, kv, att);
    sgemm_kernel<<<dim3(DIM_ / 128, ROWS_ / 128), 256>>>(att, Wo, o, ROWS_, DIM_, HID_);
    ln_kernel<<<ROWS_, 256>>>(o, gout, out);
}

// round 6
// speedup vs baseline: 1.4774x; 1.4774x over previous
#include <cuda_runtime.h>
#include <math.h>

#define B_ 4
#define N_ 4096
#define J_ 512
#define DIM_ 1024
#define CTX_ 768
#define HEADS_ 16
#define DH_ 64
#define HID_ 1024
#define ROWS_ (B_ * N_)          // 16384
#define CTXROWS_ (B_ * J_)       // 2048
#define KVW_ (2 * HID_)          // 2048

// ---------------- scratch (device globals; no allocation allowed) ----------------
__device__ float g_xn[(size_t)ROWS_ * DIM_];
__device__ float g_q[(size_t)ROWS_ * HID_];
__device__ float g_kv[(size_t)CTXROWS_ * KVW_];
__device__ float g_att[(size_t)ROWS_ * HID_];
__device__ float g_o[(size_t)ROWS_ * DIM_];
__device__ unsigned char g_fullmask[B_ * J_];

// ---------------- mask prep with dtype sniffing ----------------
__global__ void prep_mask_kernel(const void* __restrict__ mraw) {
    __shared__ int four_byte;
    if (threadIdx.x == 0) {
        const unsigned int* mi = (const unsigned int*)mraw;
        int ok = 1;
        for (int i = 0; i < (J_ - 1); i++) {
            unsigned int v = mi[i];
            if (!(v == 0u || v == 1u || v == 0x3F800000u)) { ok = 0; break; }
        }
        four_byte = ok;
    }
    __syncthreads();
    const int f = four_byte;
    for (int idx = threadIdx.x; idx < B_ * J_; idx += blockDim.x) {
        int b = idx >> 9;
        int j = idx & (J_ - 1);
        unsigned char m;
        if (j == 0) {
            m = 1;  // full_mask padded True at j==0
        } else {
            int off = b * (J_ - 1) + (j - 1);
            if (f) m = (((const unsigned int*)mraw)[off] != 0u) ? 1 : 0;
            else   m = (((const unsigned char*)mraw)[off] != 0) ? 1 : 0;
        }
        g_fullmask[idx] = m;
    }
}

// ---------------- gamma-only LayerNorm over 1024 cols ----------------
__global__ void ln_kernel(const float* __restrict__ in, const float* __restrict__ gamma,
                          float* __restrict__ out) {
    __shared__ float red_s[8];
    __shared__ float red_q[8];
    const size_t row = blockIdx.x;
    const int t = threadIdx.x;  // 256 threads, one float4 each
    float4 v = ((const float4*)(in + row * DIM_))[t];
    float s = v.x + v.y + v.z + v.w;
    float q = v.x * v.x + v.y * v.y + v.z * v.z + v.w * v.w;
#pragma unroll
    for (int o = 16; o > 0; o >>= 1) {
        s += __shfl_xor_sync(0xffffffffu, s, o);
        q += __shfl_xor_sync(0xffffffffu, q, o);
    }
    const int w = t >> 5, lane = t & 31;
    if (lane == 0) { red_s[w] = s; red_q[w] = q; }
    __syncthreads();
    float ts = 0.f, tq = 0.f;
#pragma unroll
    for (int i = 0; i < 8; i++) { ts += red_s[i]; tq += red_q[i]; }
    const float mu = ts * (1.0f / DIM_);
    const float var = tq * (1.0f / DIM_) - mu * mu;
    const float rs = rsqrtf(var + 1e-5f);
    float4 g = ((const float4*)gamma)[t];
    float4 o4;
    o4.x = (v.x - mu) * rs * g.x;
    o4.y = (v.y - mu) * rs * g.y;
    o4.z = (v.z - mu) * rs * g.z;
    o4.w = (v.w - mu) * rs * g.w;
    ((float4*)(out + row * DIM_))[t] = o4;
}

// ---------------- tf32 tensor-core GEMM: C[M,N] = A[M,K] @ B[K,N] -------------
// BM=BN=128, BK=16, 256 threads = 8 warps (2m x 4n), warp tile 64x32,
// mma.sync.m16n8k8 tf32, 4x4 mma tiles per warp. fp32 -> tf32 (cvt.rna) at
// smem-store time. Double-buffered smem, one barrier per k-tile.
// As[m][k] pad to 20 cols, Bs[k][n] pad to 136: conflict-free fragment loads.
__device__ __forceinline__ unsigned int f2tf(float f) {
    unsigned int r;
    asm("cvt.rna.tf32.f32 %0, %1;" : "=r"(r) : "f"(f));
    return r;
}

__global__ void __launch_bounds__(256)
tf32gemm_kernel(const float* __restrict__ A, const float* __restrict__ Bm,
                float* __restrict__ C, int M, int N, int K) {
    __shared__ unsigned int As[2][128][20];
    __shared__ unsigned int Bs[2][16][136];
    const int tx = threadIdx.x;
    const int lane = tx & 31;
    const int wid = tx >> 5;
    const int wm0 = (wid & 1) * 64;   // warp m offset
    const int wn0 = (wid >> 1) * 32;  // warp n offset
    const int gr = lane >> 2;         // groupID 0..7
    const int gc = lane & 3;          // threadID_in_group 0..3

    const float* Ablk = A + (size_t)blockIdx.y * 128 * K;
    const float* Bblk = Bm + (size_t)blockIdx.x * 128;

    // A tile loader: 128x16 floats = 512 float4; thread covers e = tx, tx+256.
    // e -> m = e>>2, kq = e&3  (A row-major: Ablk[m*K + k0 + kq*4 ..])
    // B tile loader: 16x128 floats = 512 float4; e -> kr = e>>5, nq = e&31.
    const int a_m0 = tx >> 2, a_kq = tx & 3;            // e0 = tx
    const int a_m1 = (tx + 256) >> 2;                   // e1 (same kq)
    const int b_kr0 = tx >> 5, b_nq = tx & 31;          // e0
    const int b_kr1 = (tx + 256) >> 5;                  // e1 (same nq)

    float acc[4][4][4];
#pragma unroll
    for (int i = 0; i < 4; i++)
#pragma unroll
        for (int j = 0; j < 4; j++)
#pragma unroll
            for (int l = 0; l < 4; l++) acc[i][j][l] = 0.f;

    // prologue: tile 0 -> cvt -> smem buf 0
    {
        float4 a0 = *(const float4*)(Ablk + (size_t)a_m0 * K + a_kq * 4);
        float4 a1 = *(const float4*)(Ablk + (size_t)a_m1 * K + a_kq * 4);
        float4 b0 = *(const float4*)(Bblk + (size_t)b_kr0 * N + b_nq * 4);
        float4 b1 = *(const float4*)(Bblk + (size_t)b_kr1 * N + b_nq * 4);
        As[0][a_m0][a_kq * 4 + 0] = f2tf(a0.x);
        As[0][a_m0][a_kq * 4 + 1] = f2tf(a0.y);
        As[0][a_m0][a_kq * 4 + 2] = f2tf(a0.z);
        As[0][a_m0][a_kq * 4 + 3] = f2tf(a0.w);
        As[0][a_m1][a_kq * 4 + 0] = f2tf(a1.x);
        As[0][a_m1][a_kq * 4 + 1] = f2tf(a1.y);
        As[0][a_m1][a_kq * 4 + 2] = f2tf(a1.z);
        As[0][a_m1][a_kq * 4 + 3] = f2tf(a1.w);
        Bs[0][b_kr0][b_nq * 4 + 0] = f2tf(b0.x);
        Bs[0][b_kr0][b_nq * 4 + 1] = f2tf(b0.y);
        Bs[0][b_kr0][b_nq * 4 + 2] = f2tf(b0.z);
        Bs[0][b_kr0][b_nq * 4 + 3] = f2tf(b0.w);
        Bs[0][b_kr1][b_nq * 4 + 0] = f2tf(b1.x);
        Bs[0][b_kr1][b_nq * 4 + 1] = f2tf(b1.y);
        Bs[0][b_kr1][b_nq * 4 + 2] = f2tf(b1.z);
        Bs[0][b_kr1][b_nq * 4 + 3] = f2tf(b1.w);
    }
    __syncthreads();

    int p = 0;
#pragma unroll 1
    for (int k0 = 0; k0 < K; k0 += 16) {
        const int has_next = (k0 + 16 < K);
        float4 pa0, pa1, pb0, pb1;
        if (has_next) {
            pa0 = *(const float4*)(Ablk + (size_t)a_m0 * K + (k0 + 16) + a_kq * 4);
            pa1 = *(const float4*)(Ablk + (size_t)a_m1 * K + (k0 + 16) + a_kq * 4);
            pb0 = *(const float4*)(Bblk + (size_t)(k0 + 16 + b_kr0) * N + b_nq * 4);
            pb1 = *(const float4*)(Bblk + (size_t)(k0 + 16 + b_kr1) * N + b_nq * 4);
        }
#pragma unroll
        for (int k8 = 0; k8 < 16; k8 += 8) {
            unsigned int af[4][4], bf[4][2];
#pragma unroll
            for (int mt = 0; mt < 4; mt++) {
                const int m = wm0 + mt * 16;
                af[mt][0] = As[p][m + gr][k8 + gc];
                af[mt][1] = As[p][m + gr + 8][k8 + gc];
                af[mt][2] = As[p][m + gr][k8 + gc + 4];
                af[mt][3] = As[p][m + gr + 8][k8 + gc + 4];
            }
#pragma unroll
            for (int nt = 0; nt < 4; nt++) {
                const int n = wn0 + nt * 8;
                bf[nt][0] = Bs[p][k8 + gc][n + gr];
                bf[nt][1] = Bs[p][k8 + gc + 4][n + gr];
            }
#pragma unroll
            for (int mt = 0; mt < 4; mt++)
#pragma unroll
                for (int nt = 0; nt < 4; nt++) {
                    asm volatile(
                        "mma.sync.aligned.m16n8k8.row.col.f32.tf32.tf32.f32 "
                        "{%0,%1,%2,%3}, {%4,%5,%6,%7}, {%8,%9}, {%0,%1,%2,%3};"
                        : "+f"(acc[mt][nt][0]), "+f"(acc[mt][nt][1]),
                          "+f"(acc[mt][nt][2]), "+f"(acc[mt][nt][3])
                        : "r"(af[mt][0]), "r"(af[mt][1]), "r"(af[mt][2]), "r"(af[mt][3]),
                          "r"(bf[nt][0]), "r"(bf[nt][1]));
                }
        }
        if (has_next) {
            const int np = p ^ 1;
            As[np][a_m0][a_kq * 4 + 0] = f2tf(pa0.x);
            As[np][a_m0][a_kq * 4 + 1] = f2tf(pa0.y);
            As[np][a_m0][a_kq * 4 + 2] = f2tf(pa0.z);
            As[np][a_m0][a_kq * 4 + 3] = f2tf(pa0.w);
            As[np][a_m1][a_kq * 4 + 0] = f2tf(pa1.x);
            As[np][a_m1][a_kq * 4 + 1] = f2tf(pa1.y);
            As[np][a_m1][a_kq * 4 + 2] = f2tf(pa1.z);
            As[np][a_m1][a_kq * 4 + 3] = f2tf(pa1.w);
            Bs[np][b_kr0][b_nq * 4 + 0] = f2tf(pb0.x);
            Bs[np][b_kr0][b_nq * 4 + 1] = f2tf(pb0.y);
            Bs[np][b_kr0][b_nq * 4 + 2] = f2tf(pb0.z);
            Bs[np][b_kr0][b_nq * 4 + 3] = f2tf(pb0.w);
            Bs[np][b_kr1][b_nq * 4 + 0] = f2tf(pb1.x);
            Bs[np][b_kr1][b_nq * 4 + 1] = f2tf(pb1.y);
            Bs[np][b_kr1][b_nq * 4 + 2] = f2tf(pb1.z);
            Bs[np][b_kr1][b_nq * 4 + 3] = f2tf(pb1.w);
            __syncthreads();
            p = np;
        }
    }

    // epilogue: c0,c1 = (row=gr, col=2*gc, +1); c2,c3 = row+8
#pragma unroll
    for (int mt = 0; mt < 4; mt++) {
#pragma unroll
        for (int nt = 0; nt < 4; nt++) {
            const size_t row0 = (size_t)blockIdx.y * 128 + wm0 + mt * 16 + gr;
            const size_t col = (size_t)blockIdx.x * 128 + wn0 + nt * 8 + gc * 2;
            float2 v01 = make_float2(acc[mt][nt][0], acc[mt][nt][1]);
            float2 v23 = make_float2(acc[mt][nt][2], acc[mt][nt][3]);
            *(float2*)(C + row0 * N + col) = v01;
            *(float2*)(C + (row0 + 8) * N + col) = v23;
        }
    }
}

// ---------------- attention: one CTA per (b, h, 64 Q rows) ----------------
#define QK_PAD 68
#define S_PAD 520
#define ATT_SMEM_FLOATS (2 * 64 * QK_PAD + 64 * S_PAD)
#define ATT_SMEM_BYTES (ATT_SMEM_FLOATS * 4)
#define SCALE_ 0.125f  // DIM_HEAD^-0.5

__global__ void __launch_bounds__(256)
attn_kernel(const float* __restrict__ q, const float* __restrict__ kv,
            float* __restrict__ outp) {
    extern __shared__ float sm[];
    float* Qt = sm;                    // [64 d][QK_PAD] transposed Q tile
    float* KV = sm + 64 * QK_PAD;      // K chunk transposed / V chunk row-major
    float* S  = sm + 2 * 64 * QK_PAD;  // [64 rows][S_PAD]
    const int tx = threadIdx.x;
    const int n0 = blockIdx.x * 64;
    const int h = blockIdx.y;
    const int b = blockIdx.z;
    const int r0 = (tx >> 4) * 4;
    const int c0 = (tx & 15) * 4;

    const float* qbase = q + ((size_t)(b * N_ + n0) * HID_) + h * DH_;
    for (int e = tx; e < 64 * 64; e += 256) {
        int i = e >> 6, d = e & 63;
        Qt[d * QK_PAD + i] = qbase[(size_t)i * HID_ + d];
    }
    __syncthreads();

    for (int jc = 0; jc < 8; jc++) {
        const int jbase = jc * 64;
        const float* kbase = kv + ((size_t)(b * J_ + jbase) * KVW_) + h * DH_;
        for (int e = tx; e < 64 * 64; e += 256) {
            int j = e >> 6, d = e & 63;
            KV[d * QK_PAD + j] = kbase[(size_t)j * KVW_ + d];
        }
        __syncthreads();
        float acc[4][4];
#pragma unroll
        for (int i = 0; i < 4; i++)
#pragma unroll
            for (int j = 0; j < 4; j++) acc[i][j] = 0.f;
#pragma unroll
        for (int d = 0; d < 64; d++) {
            float a[4], bk[4];
#pragma unroll
            for (int i = 0; i < 4; i++) a[i] = Qt[d * QK_PAD + r0 + i];
#pragma unroll
            for (int j = 0; j < 4; j++) bk[j] = KV[d * QK_PAD + c0 + j];
#pragma unroll
            for (int i = 0; i < 4; i++)
#pragma unroll
                for (int j = 0; j < 4; j++) acc[i][j] = fmaf(a[i], bk[j], acc[i][j]);
        }
#pragma unroll
        for (int i = 0; i < 4; i++)
#pragma unroll
            for (int j = 0; j < 4; j++) {
                int jg = jbase + c0 + j;
                S[(r0 + i) * S_PAD + jg] =
                    g_fullmask[b * J_ + jg] ? acc[i][j] * SCALE_ : -1e30f;
            }
        __syncthreads();
    }

    {
        const int w = tx >> 5, lane = tx & 31;
        for (int rr = 0; rr < 8; rr++) {
            float* srow = S + (w * 8 + rr) * S_PAD;
            float mx = -1e30f;
            for (int j = lane; j < J_; j += 32) mx = fmaxf(mx, srow[j]);
#pragma unroll
            for (int o = 16; o > 0; o >>= 1) mx = fmaxf(mx, __shfl_xor_sync(0xffffffffu, mx, o));
            float sum = 0.f;
            for (int j = lane; j < J_; j += 32) {
                float e = expf(srow[j] - mx);
                srow[j] = e;
                sum += e;
            }
#pragma unroll
            for (int o = 16; o > 0; o >>= 1) sum += __shfl_xor_sync(0xffffffffu, sum, o);
            float inv = 1.0f / sum;
            for (int j = lane; j < J_; j += 32) srow[j] *= inv;
        }
    }
    __syncthreads();

    float o[4][4];
#pragma unroll
    for (int i = 0; i < 4; i++)
#pragma unroll
        for (int j = 0; j < 4; j++) o[i][j] = 0.f;
    for (int jc = 0; jc < 8; jc++) {
        const int jbase = jc * 64;
        const float* vbase = kv + ((size_t)(b * J_ + jbase) * KVW_) + HID_ + h * DH_;
        for (int e = tx; e < 64 * 64; e += 256) {
            int j = e >> 6, t = e & 63;
            KV[j * QK_PAD + t] = vbase[(size_t)j * KVW_ + t];
        }
        __syncthreads();
#pragma unroll 8
        for (int j = 0; j < 64; j++) {
            float p[4], v4[4];
#pragma unroll
            for (int i = 0; i < 4; i++) p[i] = S[(r0 + i) * S_PAD + jbase + j];
#pragma unroll
            for (int t = 0; t < 4; t++) v4[t] = KV[j * QK_PAD + c0 + t];
#pragma unroll
            for (int i = 0; i < 4; i++)
#pragma unroll
                for (int t = 0; t < 4; t++) o[i][t] = fmaf(p[i], v4[t], o[i][t]);
        }
        __syncthreads();
    }
    float* ob = outp + ((size_t)(b * N_ + n0 + r0) * HID_) + h * DH_ + c0;
#pragma unroll
    for (int i = 0; i < 4; i++) {
        float4 w;
        w.x = o[i][0]; w.y = o[i][1]; w.z = o[i][2]; w.w = o[i][3];
        *(float4*)(ob + (size_t)i * HID_) = w;
    }
}

// ---------------- launch ----------------
extern "C" void kernel_launch(void* const* d_in, const int* in_sizes, int n_in,
                              void* d_out, int out_size) {
    const float* x    = (const float*)d_in[0];
    const float* ctx  = (const float*)d_in[1];
    const void*  mask = d_in[2];
    const float* gx   = (const float*)d_in[3];
    const float* Wq   = (const float*)d_in[4];
    const float* Wkv  = (const float*)d_in[5];
    const float* Wo   = (const float*)d_in[6];
    const float* gout = (const float*)d_in[7];
    float* out = (float*)d_out;

    float *xn, *q, *kv, *att, *o;
    cudaGetSymbolAddress((void**)&xn, g_xn);
    cudaGetSymbolAddress((void**)&q, g_q);
    cudaGetSymbolAddress((void**)&kv, g_kv);
    cudaGetSymbolAddress((void**)&att, g_att);
    cudaGetSymbolAddress((void**)&o, g_o);

    cudaFuncSetAttribute(attn_kernel, cudaFuncAttributeMaxDynamicSharedMemorySize,
                         ATT_SMEM_BYTES);

    prep_mask_kernel<<<1, 512>>>(mask);
    ln_kernel<<<ROWS_, 256>>>(x, gx, xn);
    tf32gemm_kernel<<<dim3(HID_ / 128, ROWS_ / 128), 256>>>(xn, Wq, q, ROWS_, HID_, DIM_);
    tf32gemm_kernel<<<dim3(KVW_ / 128, CTXROWS_ / 128), 256>>>(ctx, Wkv, kv, CTXROWS_, KVW_, CTX_);
    attn_kernel<<<dim3(N_ / 64, HEADS_, B_), 256, ATT_SMEM_BYTES>>>(q, kv, att);
    tf32gemm_kernel<<<dim3(DIM_ / 128, ROWS_ / 128), 256>>>(att, Wo, o, ROWS_, DIM_, HID_);
    ln_kernel<<<ROWS_, 256>>>(o, gout, out);
}